// round 1
// baseline (speedup 1.0000x reference)
#include <cuda_runtime.h>
#include <cstdint>

// ---------------- configuration ----------------
#define THREADS   256
#define IPT       8                 // items per thread
#define TILE      (THREADS * IPT)   // 2048 elements per block
#define NEXP      64                // num_experts (fixed by problem instance)
#define MAX_B     1024              // max blocks supported by scratch arrays
#define SCAN_THREADS 1024

// ---------------- scratch (static device globals; no runtime alloc) --------
__device__ unsigned int g_blockHist[NEXP * MAX_B];
__device__ unsigned int g_offsets[NEXP * MAX_B];

// ---------------- kernel 1: per-block expert histogram ----------------
__global__ void hist_kernel(const int* __restrict__ experts, int total, int B) {
    __shared__ unsigned int sh[NEXP];
    int t = threadIdx.x;
    if (t < NEXP) sh[t] = 0u;
    __syncthreads();

    int base = blockIdx.x * TILE;
#pragma unroll
    for (int r = 0; r < IPT; r++) {
        int idx = base + r * THREADS + t;   // striped, coalesced
        if (idx < total) {
            int e = experts[idx];
            atomicAdd(&sh[e], 1u);
        }
    }
    __syncthreads();
    // expert-major layout: all blocks of expert 0, then expert 1, ...
    if (t < NEXP) g_blockHist[t * B + blockIdx.x] = sh[t];
}

// ---------------- kernel 2: single-block exclusive scan + totals ----------
__device__ __forceinline__ unsigned int warp_incl_scan(unsigned int v) {
    int lane = threadIdx.x & 31;
#pragma unroll
    for (int d = 1; d < 32; d <<= 1) {
        unsigned int n = __shfl_up_sync(0xFFFFFFFFu, v, d);
        if (lane >= d) v += n;
    }
    return v;
}

__global__ void scan_kernel(float* __restrict__ counts_out, int total, int B) {
    const int M = NEXP * B;
    int t    = threadIdx.x;
    int lane = t & 31;
    int wid  = t >> 5;

    int per   = (M + SCAN_THREADS - 1) / SCAN_THREADS;
    int start = t * per;
    int end   = start + per; if (end > M) end = M;

    // local sequential sum
    unsigned int sum = 0;
    for (int i = start; i < end; i++) sum += g_blockHist[i];

    // block-wide exclusive scan of per-thread sums (32 warps)
    unsigned int incl = warp_incl_scan(sum);
    __shared__ unsigned int wsum[32];
    if (lane == 31) wsum[wid] = incl;
    __syncthreads();
    if (wid == 0) {
        unsigned int w = wsum[lane];
        unsigned int wincl = warp_incl_scan(w);
        wsum[lane] = wincl - w;   // exclusive warp offsets
    }
    __syncthreads();
    unsigned int run = (incl - sum) + wsum[wid];   // thread-exclusive prefix

    // write exclusive offsets
    for (int i = start; i < end; i++) {
        unsigned int v = g_blockHist[i];
        g_offsets[i] = run;
        run += v;
    }
    __syncthreads();

    // per-expert totals -> float counts output
    if (t < NEXP) {
        unsigned int s = g_offsets[t * B];
        unsigned int e = (t == NEXP - 1) ? (unsigned int)total : g_offsets[(t + 1) * B];
        counts_out[t] = (float)(e - s);
    }
}

// ---------------- kernel 3: stable scatter ----------------
__global__ void scatter_kernel(const float* __restrict__ scores,
                               const int* __restrict__ experts,
                               const int* __restrict__ topk_ptr,
                               float* __restrict__ out_scores,
                               float* __restrict__ out_tok,
                               int total, int B) {
    __shared__ unsigned int sh_off[NEXP];        // base offset for this block
    __shared__ unsigned int running[NEXP];       // counts from prior rounds
    __shared__ unsigned int warp_hist[THREADS / 32][NEXP];

    const int t    = threadIdx.x;
    const int lane = t & 31;
    const int wid  = t >> 5;
    const int b    = blockIdx.x;
    const int topk = *topk_ptr;

    if (t < NEXP) {
        sh_off[t]  = g_offsets[t * B + b];
        running[t] = 0u;
    }
    for (int i = t; i < (THREADS / 32) * NEXP; i += THREADS)
        ((unsigned int*)warp_hist)[i] = 0u;
    __syncthreads();

    const int base = b * TILE;
#pragma unroll
    for (int r = 0; r < IPT; r++) {
        int idx = base + r * THREADS + t;            // striped => flat order = (r, t) order
        int e   = (idx < total) ? experts[idx] : 0x7FFFFFFF;
        float sc = (idx < total) ? scores[idx] : 0.0f;

        unsigned int mask = __match_any_sync(0xFFFFFFFFu, e);
        unsigned int lt   = (1u << lane) - 1u;
        int lane_rank = __popc(mask & lt);
        int leader    = __ffs(mask) - 1;
        if (lane == leader && e < NEXP)
            warp_hist[wid][e] = (unsigned int)__popc(mask);
        __syncthreads();

        if (e < NEXP) {
            unsigned int pre = running[e];
            for (int w = 0; w < wid; w++) pre += warp_hist[w][e];
            unsigned int pos = sh_off[e] + pre + (unsigned int)lane_rank;
            out_scores[pos] = sc;
            out_tok[pos]    = (float)(idx / topk);
        }
        __syncthreads();

        // accumulate this round's counts and clear warp_hist for next round
        if (t < NEXP) {
            unsigned int s = 0;
#pragma unroll
            for (int w = 0; w < THREADS / 32; w++) {
                s += warp_hist[w][t];
                warp_hist[w][t] = 0u;
            }
            running[t] += s;
        }
        __syncthreads();
    }
}

// ---------------- launch ----------------
extern "C" void kernel_launch(void* const* d_in, const int* in_sizes, int n_in,
                              void* d_out, int out_size) {
    const float* scores   = (const float*)d_in[0];  // top_scores, N*K f32
    const int*   experts  = (const int*)  d_in[1];  // selected_experts_indices, N*K i32
    const int*   topk_ptr = (const int*)  d_in[3];  // top_k scalar on device

    int total = in_sizes[0];                        // N * top_k = 524288
    int B = (total + TILE - 1) / TILE;              // 256 blocks
    if (B > MAX_B) B = MAX_B;                       // (defensive; instance fits)

    float* out        = (float*)d_out;
    float* out_scores = out;                        // [0, total)
    float* out_tok    = out + total;                // [total, 2*total)
    float* out_counts = out + 2 * (size_t)total;    // [2*total, 2*total + 64)

    hist_kernel<<<B, THREADS>>>(experts, total, B);
    scan_kernel<<<1, SCAN_THREADS>>>(out_counts, total, B);
    scatter_kernel<<<B, THREADS>>>(scores, experts, topk_ptr,
                                   out_scores, out_tok, total, B);
}

// round 3
// speedup vs baseline: 1.2094x; 1.2094x over previous
#include <cuda_runtime.h>
#include <cstdint>

// ---------------- configuration ----------------
#define THREADS   256
#define NWARP     (THREADS / 32)
#define IPT       8                 // items per thread
#define TILE      (THREADS * IPT)   // 2048 elements per block
#define NEXP      64                // num_experts (fixed by problem instance)
#define MAX_B     1024
#define SCAN_THREADS 1024

// ---------------- scratch (static device globals; no runtime alloc) --------
__device__ unsigned int g_blockHist[NEXP * MAX_B];
__device__ unsigned int g_offsets[NEXP * MAX_B];

// ---------------- kernel 1: per-block expert histogram (int4 loads) -------
__global__ void hist_kernel(const int4* __restrict__ experts4, int total4, int B) {
    __shared__ unsigned int sh[NEXP];
    int t = threadIdx.x;
    if (t < NEXP) sh[t] = 0u;
    __syncthreads();

    int base4 = blockIdx.x * (TILE / 4);
    // issue both vector loads before any atomic (MLP=2x128B lines)
    int i0 = base4 + t;
    int i1 = base4 + THREADS + t;
    int4 a = (i0 < total4) ? experts4[i0] : make_int4(-1, -1, -1, -1);
    int4 b = (i1 < total4) ? experts4[i1] : make_int4(-1, -1, -1, -1);

    if (i0 < total4) {
        atomicAdd(&sh[a.x], 1u); atomicAdd(&sh[a.y], 1u);
        atomicAdd(&sh[a.z], 1u); atomicAdd(&sh[a.w], 1u);
    }
    if (i1 < total4) {
        atomicAdd(&sh[b.x], 1u); atomicAdd(&sh[b.y], 1u);
        atomicAdd(&sh[b.z], 1u); atomicAdd(&sh[b.w], 1u);
    }
    __syncthreads();
    // expert-major layout: all blocks of expert 0, then expert 1, ...
    if (t < NEXP) g_blockHist[t * B + blockIdx.x] = sh[t];
}

// ---------------- kernel 2: single-block exclusive scan + totals ----------
__device__ __forceinline__ unsigned int warp_incl_scan(unsigned int v) {
    int lane = threadIdx.x & 31;
#pragma unroll
    for (int d = 1; d < 32; d <<= 1) {
        unsigned int n = __shfl_up_sync(0xFFFFFFFFu, v, d);
        if (lane >= d) v += n;
    }
    return v;
}

__global__ void scan_kernel(float* __restrict__ counts_out, int total, int B) {
    const int M = NEXP * B;          // 16384 for B=256
    int t    = threadIdx.x;
    int lane = t & 31;
    int wid  = t >> 5;

    int per   = (M + SCAN_THREADS - 1) / SCAN_THREADS;   // 16
    int start = t * per;
    int end   = start + per; if (end > M) end = M;

    // local sequential sum (vectorized when aligned: per is a multiple of 4)
    unsigned int sum = 0;
    if ((per & 3) == 0 && start + per <= M) {
        const uint4* p = (const uint4*)&g_blockHist[start];
#pragma unroll 4
        for (int i = 0; i < per / 4; i++) {
            uint4 v = p[i];
            sum += v.x + v.y + v.z + v.w;
        }
    } else {
        for (int i = start; i < end; i++) sum += g_blockHist[i];
    }

    // block-wide exclusive scan of per-thread sums (32 warps)
    unsigned int incl = warp_incl_scan(sum);
    __shared__ unsigned int wsum[32];
    if (lane == 31) wsum[wid] = incl;
    __syncthreads();
    if (wid == 0) {
        unsigned int w = wsum[lane];
        unsigned int wincl = warp_incl_scan(w);
        wsum[lane] = wincl - w;
    }
    __syncthreads();
    unsigned int run = (incl - sum) + wsum[wid];

    for (int i = start; i < end; i++) {
        unsigned int v = g_blockHist[i];
        g_offsets[i] = run;
        run += v;
    }
    __syncthreads();

    if (t < NEXP) {
        unsigned int s = g_offsets[t * B];
        unsigned int e = (t == NEXP - 1) ? (unsigned int)total : g_offsets[(t + 1) * B];
        counts_out[t] = (float)(e - s);
    }
}

// ---------------- kernel 3: stable scatter, 3 barriers total --------------
__global__ void scatter_kernel(const float* __restrict__ scores,
                               const int* __restrict__ experts,
                               const int* __restrict__ topk_ptr,
                               float* __restrict__ out_scores,
                               float* __restrict__ out_tok,
                               int total, int B) {
    // cnt[(r*NWARP + w)*NEXP + e] : count of expert e in (round r, warp w)
    __shared__ unsigned int cnt[IPT * NWARP * NEXP];   // 16 KB
    __shared__ unsigned int sh_off[NEXP];

    const int t    = threadIdx.x;
    const int lane = t & 31;
    const int wid  = t >> 5;
    const int b    = blockIdx.x;

    const int topk = *topk_ptr;
    const bool pow2 = (topk & (topk - 1)) == 0;
    const int shift = pow2 ? (31 - __clz(topk)) : 0;

    if (t < NEXP) sh_off[t] = g_offsets[t * B + b];
#pragma unroll
    for (int i = t; i < IPT * NWARP * NEXP; i += THREADS) cnt[i] = 0u;
    __syncthreads();

    const int base = b * TILE;
    int   e[IPT];
    float sc[IPT];
    int   rk[IPT];

    // Pass 1: load, compute warp-local stable ranks per round, fill cnt.
    // Each (round, warp) owns an exclusive 64-word cnt slice -> no races.
#pragma unroll
    for (int r = 0; r < IPT; r++) {
        int idx = base + r * THREADS + t;               // striped = flat order
        bool ok = idx < total;
        e[r]  = ok ? experts[idx] : -1;
        sc[r] = ok ? scores[idx] : 0.0f;

        unsigned int mask = __match_any_sync(0xFFFFFFFFu, e[r]);
        unsigned int lt   = (1u << lane) - 1u;
        rk[r] = __popc(mask & lt);
        int leader = __ffs(mask) - 1;
        if (lane == leader && (unsigned)e[r] < NEXP)
            cnt[(r * NWARP + wid) * NEXP + e[r]] = (unsigned int)__popc(mask);
    }
    __syncthreads();

    // Pass 2: per-expert exclusive scan over the 64 (round,warp) slots.
    // Thread t (< 64) handles expert t; stride-NEXP words -> bank-conflict-free.
    if (t < NEXP) {
        unsigned int run = 0;
#pragma unroll
        for (int k = 0; k < IPT * NWARP; k++) {
            unsigned int v = cnt[k * NEXP + t];
            cnt[k * NEXP + t] = run;
            run += v;
        }
    }
    __syncthreads();

    // Pass 3: all stores, no further syncs.
#pragma unroll
    for (int r = 0; r < IPT; r++) {
        if ((unsigned)e[r] < NEXP) {
            int idx = base + r * THREADS + t;
            unsigned int pos = sh_off[e[r]]
                             + cnt[(r * NWARP + wid) * NEXP + e[r]]
                             + (unsigned int)rk[r];
            int tok = pow2 ? (idx >> shift) : (idx / topk);
            out_scores[pos] = sc[r];
            out_tok[pos]    = (float)tok;
        }
    }
}

// ---------------- launch ----------------
extern "C" void kernel_launch(void* const* d_in, const int* in_sizes, int n_in,
                              void* d_out, int out_size) {
    const float* scores   = (const float*)d_in[0];  // top_scores, N*K f32
    const int*   experts  = (const int*)  d_in[1];  // selected_experts_indices, N*K i32
    const int*   topk_ptr = (const int*)  d_in[3];  // top_k scalar on device

    int total = in_sizes[0];                        // N * top_k = 524288
    int B = (total + TILE - 1) / TILE;              // 256 blocks
    if (B > MAX_B) B = MAX_B;

    float* out        = (float*)d_out;
    float* out_scores = out;                        // [0, total)
    float* out_tok    = out + total;                // [total, 2*total)
    float* out_counts = out + 2 * (size_t)total;    // [2*total, +64)

    hist_kernel<<<B, THREADS>>>((const int4*)experts, total / 4, B);
    scan_kernel<<<1, SCAN_THREADS>>>(out_counts, total, B);
    scatter_kernel<<<B, THREADS>>>(scores, experts, topk_ptr,
                                   out_scores, out_tok, total, B);
}